// round 1
// baseline (speedup 1.0000x reference)
#include <cuda_runtime.h>
#include <math.h>

// Problem constants
constexpr int D   = 768;
constexpr int S   = 128;     // nodes with edges
constexpr int BSN = 4096;    // B*S
constexpr int NN  = 12288;   // 3*B*S nodes
constexpr int H3  = 2304;    // 3*D

// Scratch (device globals — allocation-free rule)
__device__ float g_feats[NN * D];          // feats; reused as y_all for MLP input
__device__ float g_x[NN * D];              // node state x
__device__ float g_xw[NN * D];             // xw; reused as MLP hidden h_all
__device__ float g_gh[NN * H3];            // GRU gh; reused as MLP z_all
__device__ float g_sim[S * S];
__device__ float g_nrm[S];
__device__ float g_dinv[S];
__device__ float g_deginv[S];
__device__ float g_svec[D];
__device__ float g_mvec[D];
__device__ float g_gi[H3];

// ---------------------------------------------------------------------------
// SGEMM: C[M,N] = A[M,K] * B (+bias, +relu).  TRANSB: B is [N,K] row-major.
// 128x128 tile, BK=8, 256 threads, 8x8 per-thread register tile.
// Requires M%128==0, N%128==0, K%8==0 (holds for all call sites).
// ---------------------------------------------------------------------------
template <bool TRANSB, int EPI>   // EPI: 0 none, 1 bias, 2 bias+relu
__global__ __launch_bounds__(256)
void sgemm_kernel(const float* __restrict__ A, const float* __restrict__ B,
                  const float* __restrict__ bias, float* __restrict__ C,
                  int M, int N, int K)
{
    __shared__ float As[8][128];
    __shared__ float Bs[8][128];
    const int bm  = blockIdx.y * 128;
    const int bn  = blockIdx.x * 128;
    const int tid = threadIdx.x;
    const int tx  = tid & 15;      // 16 cols of 8
    const int ty  = tid >> 4;      // 16 rows of 8
    const int lRow = tid >> 1;     // 0..127
    const int lCol = (tid & 1) * 4;

    float acc[8][8];
#pragma unroll
    for (int i = 0; i < 8; i++)
#pragma unroll
        for (int j = 0; j < 8; j++) acc[i][j] = 0.f;

    for (int k0 = 0; k0 < K; k0 += 8) {
        float4 av = *(const float4*)(A + (size_t)(bm + lRow) * K + k0 + lCol);
        As[lCol + 0][lRow] = av.x; As[lCol + 1][lRow] = av.y;
        As[lCol + 2][lRow] = av.z; As[lCol + 3][lRow] = av.w;
        if (TRANSB) {
            float4 bv = *(const float4*)(B + (size_t)(bn + lRow) * K + k0 + lCol);
            Bs[lCol + 0][lRow] = bv.x; Bs[lCol + 1][lRow] = bv.y;
            Bs[lCol + 2][lRow] = bv.z; Bs[lCol + 3][lRow] = bv.w;
        } else {
            int bk  = tid >> 5;
            int bn4 = (tid & 31) * 4;
            *(float4*)&Bs[bk][bn4] =
                *(const float4*)(B + (size_t)(k0 + bk) * N + bn + bn4);
        }
        __syncthreads();
#pragma unroll
        for (int k = 0; k < 8; k++) {
            float4 a0 = *(const float4*)&As[k][ty * 8];
            float4 a1 = *(const float4*)&As[k][ty * 8 + 4];
            float4 b0 = *(const float4*)&Bs[k][tx * 8];
            float4 b1 = *(const float4*)&Bs[k][tx * 8 + 4];
            float a[8] = {a0.x, a0.y, a0.z, a0.w, a1.x, a1.y, a1.z, a1.w};
            float b[8] = {b0.x, b0.y, b0.z, b0.w, b1.x, b1.y, b1.z, b1.w};
#pragma unroll
            for (int i = 0; i < 8; i++)
#pragma unroll
                for (int j = 0; j < 8; j++)
                    acc[i][j] = fmaf(a[i], b[j], acc[i][j]);
        }
        __syncthreads();
    }

#pragma unroll
    for (int i = 0; i < 8; i++) {
        int m = bm + ty * 8 + i;
#pragma unroll
        for (int j = 0; j < 8; j += 4) {
            int n = bn + tx * 8 + j;
            float4 v = make_float4(acc[i][j], acc[i][j + 1], acc[i][j + 2], acc[i][j + 3]);
            if (EPI >= 1) {
                v.x += bias[n]; v.y += bias[n + 1]; v.z += bias[n + 2]; v.w += bias[n + 3];
            }
            if (EPI == 2) {
                v.x = fmaxf(v.x, 0.f); v.y = fmaxf(v.y, 0.f);
                v.z = fmaxf(v.z, 0.f); v.w = fmaxf(v.w, 0.f);
            }
            *(float4*)(C + (size_t)m * N + n) = v;
        }
    }
}

// ---------------------------------------------------------------------------
// feats[n,d] = h_{d%3}.flat[n*256 + d/3]
// ---------------------------------------------------------------------------
__global__ void k_gather(const float* __restrict__ a, const float* __restrict__ b,
                         const float* __restrict__ c)
{
    int o = blockIdx.x * 256 + threadIdx.x;
    int n = o / D;
    int d = o - n * D;
    int t = d % 3;
    const float* s = (t == 0) ? a : ((t == 1) ? b : c);
    g_feats[o] = s[n * (D / 3) + d / 3];
}

// Row norms of the first 128 feature rows
__global__ void k_norm()
{
    int i = blockIdx.x;
    float s = 0.f;
    for (int k = threadIdx.x; k < D; k += 256) {
        float v = g_feats[i * D + k];
        s = fmaf(v, v, s);
    }
    __shared__ float sh[256];
    sh[threadIdx.x] = s; __syncthreads();
    for (int t = 128; t > 0; t >>= 1) {
        if (threadIdx.x < t) sh[threadIdx.x] += sh[threadIdx.x + t];
        __syncthreads();
    }
    if (threadIdx.x == 0) g_nrm[i] = fmaxf(sqrtf(sh[0]), 1e-8f);
}

// Raw cosine-sim matrix (128x128). Block i: 8 warps x 16 j's each.
__global__ void k_sim()
{
    int i = blockIdx.x;
    __shared__ float fi[D];
    for (int k = threadIdx.x; k < D; k += 256) fi[k] = g_feats[i * D + k];
    __syncthreads();
    int warp = threadIdx.x >> 5, lane = threadIdx.x & 31;
    float ni = g_nrm[i];
    for (int jj = 0; jj < 16; jj++) {
        int j = warp * 16 + jj;
        float s = 0.f;
        for (int k = lane; k < D; k += 32) s = fmaf(fi[k], g_feats[j * D + k], s);
        for (int o = 16; o > 0; o >>= 1) s += __shfl_down_sync(0xffffffffu, s, o);
        if (lane == 0) g_sim[i * S + j] = s / (ni * g_nrm[j]);
    }
}

// Single block: min/max normalize sim in place, compute deg / dinv / 1/deg.
__global__ void k_simnorm()
{
    __shared__ float smn[256], smx[256];
    int tid = threadIdx.x;
    float mn = 1e30f, mx = -1e30f;
    for (int e = tid; e < S * S; e += 256) {
        float v = g_sim[e];
        mn = fminf(mn, v); mx = fmaxf(mx, v);
    }
    smn[tid] = mn; smx[tid] = mx;
    __syncthreads();
    for (int t = 128; t > 0; t >>= 1) {
        if (tid < t) {
            smn[tid] = fminf(smn[tid], smn[tid + t]);
            smx[tid] = fmaxf(smx[tid], smx[tid + t]);
        }
        __syncthreads();
    }
    float lo = smn[0];
    float inv = 1.f / (smx[0] - smn[0]);
    __syncthreads();
    for (int e = tid; e < S * S; e += 256) g_sim[e] = (g_sim[e] - lo) * inv;
    __syncthreads();
    if (tid < S) {
        float dg = 1.f;
        for (int i = 0; i < S; i++) dg += g_sim[i * S + tid];
        g_dinv[tid]   = rsqrtf(dg);
        g_deginv[tid] = 1.f / dg;
    }
}

// GCN output for nodes c < 128: neighbor agg + self term, +bias, relu.
__global__ void k_gcn_first(const float* __restrict__ gcn_b)
{
    int c = blockIdx.x;
    int d = blockIdx.y * 128 + threadIdx.x;
    __shared__ float col[S];
    col[threadIdx.x] = g_dinv[threadIdx.x] * g_sim[threadIdx.x * S + c];
    __syncthreads();
    float acc = 0.f;
#pragma unroll 8
    for (int i = 0; i < S; i++) acc = fmaf(col[i], g_xw[i * D + d], acc);
    float v = g_dinv[c] * acc + g_xw[c * D + d] * g_deginv[c] + gcn_b[d];
    g_x[c * D + d] = fmaxf(v, 0.f);
}

// GCN output for nodes >= 128 (deg == 1): x = relu(xw + b)
__global__ void k_gcn_rest(const float* __restrict__ gcn_b)
{
    int idx = blockIdx.x * 256 + threadIdx.x;
    int o = S * D + idx;
    int d = o % D;
    g_x[o] = fmaxf(g_xw[o] + gcn_b[d], 0.f);
}

// s[d] = sum over first 128 rows of x
__global__ void k_colsum()
{
    int d = blockIdx.x * 256 + threadIdx.x;
    float s = 0.f;
    for (int r = 0; r < S; r++) s += g_x[r * D + d];
    g_svec[d] = s;
}

// mvec = s @ W   (W is [D,D] row-major)
__global__ void k_mvec(const float* __restrict__ W)
{
    int d = blockIdx.x * 256 + threadIdx.x;
    float acc = 0.f;
    for (int k = 0; k < D; k++) acc = fmaf(g_svec[k], W[k * D + d], acc);
    g_mvec[d] = acc;
}

// gi[o] = mvec . wih[o,:] + bih[o]   (one warp per output)
__global__ void k_gi(const float* __restrict__ wih, const float* __restrict__ bih)
{
    int warp = threadIdx.x >> 5, lane = threadIdx.x & 31;
    int o = blockIdx.x * 8 + warp;
    float s = 0.f;
    for (int k = lane; k < D; k += 32) s = fmaf(g_mvec[k], wih[o * D + k], s);
    for (int off = 16; off > 0; off >>= 1) s += __shfl_down_sync(0xffffffffu, s, off);
    if (lane == 0) g_gi[o] = s + bih[o];
}

// GRU elementwise update, in place on g_x. gh already has +bhh baked in.
__global__ void k_gru(const float* __restrict__ bih)
{
    int o = blockIdx.x * 256 + threadIdx.x;
    int n = o / D;
    int d = o - n * D;
    float gir, giz, gin;
    if (n < S) { gir = g_gi[d];  giz = g_gi[D + d];  gin = g_gi[2 * D + d]; }
    else       { gir = bih[d];   giz = bih[D + d];   gin = bih[2 * D + d]; }
    size_t gb = (size_t)n * H3;
    float r  = 1.f / (1.f + expf(-(gir + g_gh[gb + d])));
    float z  = 1.f / (1.f + expf(-(giz + g_gh[gb + D + d])));
    float nn = tanhf(gin + r * g_gh[gb + 2 * D + d]);
    g_x[o] = (1.f - z) * nn + z * g_x[o];
}

// y_all = h_feature(broadcast over the 3 thirds) + relu(x); into g_feats
__global__ void k_buildy(const float* __restrict__ hfeat)
{
    int o = blockIdx.x * 256 + threadIdx.x;
    g_feats[o] = hfeat[o % (BSN * D)] + fmaxf(g_x[o], 0.f);
}

// LayerNorm over last dim (768) with per-third gamma/beta; z lives in g_gh.
__global__ void k_ln(const float* __restrict__ g1, const float* __restrict__ be1,
                     const float* __restrict__ g2, const float* __restrict__ be2,
                     const float* __restrict__ g3, const float* __restrict__ be3,
                     float* __restrict__ out)
{
    int r = blockIdx.x;
    int t = r / BSN;
    const float* gg = (t == 0) ? g1 : ((t == 1) ? g2 : g3);
    const float* bb = (t == 0) ? be1 : ((t == 1) ? be2 : be3);
    const float* z = g_gh + (size_t)r * D;
    int tid = threadIdx.x;
    float v0 = z[tid], v1 = z[tid + 256], v2 = z[tid + 512];
    __shared__ float sh[256];
    sh[tid] = v0 + v1 + v2; __syncthreads();
    for (int s = 128; s > 0; s >>= 1) {
        if (tid < s) sh[tid] += sh[tid + s];
        __syncthreads();
    }
    float mu = sh[0] * (1.f / 768.f);
    __syncthreads();
    float d0 = v0 - mu, d1 = v1 - mu, d2 = v2 - mu;
    sh[tid] = d0 * d0 + d1 * d1 + d2 * d2; __syncthreads();
    for (int s = 128; s > 0; s >>= 1) {
        if (tid < s) sh[tid] += sh[tid + s];
        __syncthreads();
    }
    float rstd = rsqrtf(sh[0] * (1.f / 768.f) + 1e-5f);
    float* o = out + (size_t)r * D;
    o[tid]       = d0 * rstd * gg[tid]       + bb[tid];
    o[tid + 256] = d1 * rstd * gg[tid + 256] + bb[tid + 256];
    o[tid + 512] = d2 * rstd * gg[tid + 512] + bb[tid + 512];
}

// ---------------------------------------------------------------------------
extern "C" void kernel_launch(void* const* d_in, const int* in_sizes, int n_in,
                              void* d_out, int out_size)
{
    const float* h_feature = (const float*)d_in[0];
    const float* h_con     = (const float*)d_in[1];
    const float* h_dep     = (const float*)d_in[2];
    const float* h_sem     = (const float*)d_in[3];
    const float* gcn_W     = (const float*)d_in[4];
    const float* gcn_b     = (const float*)d_in[5];
    const float* ggc_W     = (const float*)d_in[6];
    const float* gru_wih   = (const float*)d_in[7];
    const float* gru_whh   = (const float*)d_in[8];
    const float* gru_bih   = (const float*)d_in[9];
    const float* gru_bhh   = (const float*)d_in[10];
    const float* rW1[3]   = {(const float*)d_in[11], (const float*)d_in[17], (const float*)d_in[23]};
    const float* rb1[3]   = {(const float*)d_in[12], (const float*)d_in[18], (const float*)d_in[24]};
    const float* rW2[3]   = {(const float*)d_in[13], (const float*)d_in[19], (const float*)d_in[25]};
    const float* rb2[3]   = {(const float*)d_in[14], (const float*)d_in[20], (const float*)d_in[26]};
    const float* rg[3]    = {(const float*)d_in[15], (const float*)d_in[21], (const float*)d_in[27]};
    const float* rbeta[3] = {(const float*)d_in[16], (const float*)d_in[22], (const float*)d_in[28]};
    float* out = (float*)d_out;

    float *feats, *x, *xw, *gh;
    cudaGetSymbolAddress((void**)&feats, g_feats);
    cudaGetSymbolAddress((void**)&x,     g_x);
    cudaGetSymbolAddress((void**)&xw,    g_xw);
    cudaGetSymbolAddress((void**)&gh,    g_gh);

    // 1) feats gather + graph scalars
    k_gather<<<NN * D / 256, 256>>>(h_con, h_dep, h_sem);
    k_norm<<<S, 256>>>();
    k_sim<<<S, 256>>>();
    k_simnorm<<<1, 256>>>();

    // 2) xw = feats @ gcn_W  (12288x768x768)
    {
        dim3 g(D / 128, NN / 128);
        sgemm_kernel<false, 0><<<g, 256>>>(feats, gcn_W, nullptr, xw, NN, D, D);
    }

    // 3) GCN aggregation + relu -> g_x
    {
        dim3 g(S, D / 128);
        k_gcn_first<<<g, 128>>>(gcn_b);
    }
    k_gcn_rest<<<(NN - S) * D / 256, 256>>>(gcn_b);

    // 4) GatedGraphConv: 2 layers
    for (int l = 0; l < 2; l++) {
        k_colsum<<<3, 256>>>();
        k_mvec<<<3, 256>>>(ggc_W + (size_t)l * D * D);
        k_gi<<<H3 / 8, 256>>>(gru_wih, gru_bih);
        dim3 g(H3 / 128, NN / 128);
        sgemm_kernel<true, 1><<<g, 256>>>(x, gru_whh, gru_bhh, gh, NN, H3, D);
        k_gru<<<NN * D / 256, 256>>>(gru_bih);
    }

    // 5) y = h_feature + relu(x)  (into g_feats)
    k_buildy<<<NN * D / 256, 256>>>(h_feature);

    // 6) three residual MLPs: h = relu(yW1+b1); z = hW2+b2
    for (int t = 0; t < 3; t++) {
        size_t off = (size_t)t * BSN * D;
        dim3 g(D / 128, BSN / 128);
        sgemm_kernel<false, 2><<<g, 256>>>(feats + off, rW1[t], rb1[t], xw + off, BSN, D, D);
        sgemm_kernel<false, 1><<<g, 256>>>(xw + off, rW2[t], rb2[t], gh + off, BSN, D, D);
    }

    // 7) LayerNorm -> d_out
    k_ln<<<NN, 256>>>(rg[0], rbeta[0], rg[1], rbeta[1], rg[2], rbeta[2], out);
}

// round 3
// speedup vs baseline: 2.9030x; 2.9030x over previous
#include <cuda_runtime.h>
#include <math.h>
#include <stdint.h>

// Problem constants
constexpr int D   = 768;
constexpr int S   = 128;
constexpr int BSN = 4096;    // B*S
constexpr int NN  = 12288;   // 3*B*S
constexpr int H3  = 2304;    // 3*D

// Scratch (device globals — allocation-free rule)
__device__ float g_feats[NN * D];
__device__ float g_x[NN * D];
__device__ float g_xw[NN * D];
__device__ float g_gh[(size_t)NN * H3];
__device__ float g_sim[S * S];
__device__ float g_nrm[S];
__device__ float g_dinv[S];
__device__ float g_deginv[S];
__device__ float g_svec[D];
__device__ float g_mvec[D];
__device__ float g_gi[H3];
__device__ float g_wtg[D * D];        // gcn_W^T
__device__ float g_wt1[3 * D * D];    // rW1[t]^T
__device__ float g_wt2[3 * D * D];    // rW2[t]^T

// ============================ mma.sync helpers =============================
__device__ __forceinline__ uint32_t smem_u32(const void* p) {
    uint32_t a;
    asm("{ .reg .u64 t; cvta.to.shared.u64 t, %1; cvt.u32.u64 %0, t; }"
        : "=r"(a) : "l"(p));
    return a;
}
__device__ __forceinline__ uint32_t f2tf32(float f) {
    uint32_t u;
    asm("cvt.rna.tf32.f32 %0, %1;" : "=r"(u) : "f"(f));
    return u;
}
__device__ __forceinline__ void ldm_x4(uint32_t& r0, uint32_t& r1,
                                       uint32_t& r2, uint32_t& r3, uint32_t addr) {
    asm volatile("ldmatrix.sync.aligned.m8n8.x4.shared.b16 {%0,%1,%2,%3}, [%4];"
                 : "=r"(r0), "=r"(r1), "=r"(r2), "=r"(r3) : "r"(addr));
}
__device__ __forceinline__ void mma_tf32(float* c, const uint32_t* a,
                                         const uint32_t* b) {
    asm volatile(
        "mma.sync.aligned.m16n8k8.row.col.f32.tf32.tf32.f32 "
        "{%0,%1,%2,%3}, {%4,%5,%6,%7}, {%8,%9}, {%0,%1,%2,%3};"
        : "+f"(c[0]), "+f"(c[1]), "+f"(c[2]), "+f"(c[3])
        : "r"(a[0]), "r"(a[1]), "r"(a[2]), "r"(a[3]), "r"(b[0]), "r"(b[1]));
}

// ===========================================================================
// tf32 mma.sync GEMM: C[m,n] = sum_k A[m,k]*B[n,k] (+bias, +relu)
// Block 128x128, BK=16, 8 warps (2m x 4n), warp tile 64x32.
// Double-buffered SMEM, register prefetch, tf32 conversion at STS.
// B / bias selected per M-segment (rowSeg) to batch 3 MLP branches.
// ===========================================================================
constexpr int BM = 128, BN = 128, BK = 16, BKP = 20;

template <int EPI>  // 0 none, 1 bias, 2 bias+relu
__global__ void __launch_bounds__(256, 2) tf32_gemm(
    const float* __restrict__ A,
    const float* __restrict__ B0, const float* __restrict__ B1,
    const float* __restrict__ B2,
    const float* __restrict__ bias0, const float* __restrict__ bias1,
    const float* __restrict__ bias2,
    float* __restrict__ C, int M, int N, int K, int rowSeg)
{
    __shared__ __align__(16) float As[2][BM * BKP];
    __shared__ __align__(16) float Bs[2][BN * BKP];

    const int bm = blockIdx.y * BM;
    const int bn = blockIdx.x * BN;
    const int seg = bm / rowSeg;
    const float* Bp   = (seg == 0) ? B0 : ((seg == 1) ? B1 : B2);
    const float* bias = (seg == 0) ? bias0 : ((seg == 1) ? bias1 : bias2);

    const int tid  = threadIdx.x;
    const int lane = tid & 31;
    const int wid  = tid >> 5;
    const int wm   = (wid >> 2) * 64;   // warp m offset (0 / 64)
    const int wn   = (wid & 3) * 32;    // warp n offset (0/32/64/96)

    // GMEM load coords: thread loads 2 float4 from A and 2 from B per stage
    const int lr = tid >> 2;         // 0..63
    const int lc = (tid & 3) * 4;    // 0,4,8,12
    const float* Ag = A  + (size_t)(bm + lr) * K + lc;
    const float* Bg = Bp + (size_t)(bn + lr) * K + lc;

    const uint32_t sA = smem_u32(As);
    const uint32_t sB = smem_u32(Bs);
    // ldmatrix per-lane address components
    const uint32_t aRowOff = (uint32_t)(wm + (lane & 15)) * BKP * 4 + (lane >> 4) * 16;
    const uint32_t bRowOff = (uint32_t)(wn + (lane & 7) + ((lane >> 4) << 3)) * BKP * 4
                             + ((lane >> 3) & 1) * 16;
    // STS offsets (floats)
    const int stRow = lr * BKP + lc;

    float c[4][4][4];
#pragma unroll
    for (int i = 0; i < 4; i++)
#pragma unroll
        for (int j = 0; j < 4; j++)
#pragma unroll
            for (int q = 0; q < 4; q++) c[i][j][q] = 0.f;

    float4 pa0, pa1, pb0, pb1;
    // Prologue: load stage 0
    pa0 = *(const float4*)(Ag);
    pa1 = *(const float4*)(Ag + (size_t)64 * K);
    pb0 = *(const float4*)(Bg);
    pb1 = *(const float4*)(Bg + (size_t)64 * K);
    {
        float* a0 = &As[0][stRow];
        a0[0] = __uint_as_float(f2tf32(pa0.x)); a0[1] = __uint_as_float(f2tf32(pa0.y));
        a0[2] = __uint_as_float(f2tf32(pa0.z)); a0[3] = __uint_as_float(f2tf32(pa0.w));
        float* a1 = &As[0][stRow + 64 * BKP];
        a1[0] = __uint_as_float(f2tf32(pa1.x)); a1[1] = __uint_as_float(f2tf32(pa1.y));
        a1[2] = __uint_as_float(f2tf32(pa1.z)); a1[3] = __uint_as_float(f2tf32(pa1.w));
        float* b0 = &Bs[0][stRow];
        b0[0] = __uint_as_float(f2tf32(pb0.x)); b0[1] = __uint_as_float(f2tf32(pb0.y));
        b0[2] = __uint_as_float(f2tf32(pb0.z)); b0[3] = __uint_as_float(f2tf32(pb0.w));
        float* b1 = &Bs[0][stRow + 64 * BKP];
        b1[0] = __uint_as_float(f2tf32(pb1.x)); b1[1] = __uint_as_float(f2tf32(pb1.y));
        b1[2] = __uint_as_float(f2tf32(pb1.z)); b1[3] = __uint_as_float(f2tf32(pb1.w));
    }
    __syncthreads();

    const int NS = K / BK;
    for (int ks = 0; ks < NS; ks++) {
        const int buf = ks & 1;
        const bool more = (ks + 1) < NS;
        if (more) {
            const int k0 = (ks + 1) * BK;
            pa0 = *(const float4*)(Ag + k0);
            pa1 = *(const float4*)(Ag + (size_t)64 * K + k0);
            pb0 = *(const float4*)(Bg + k0);
            pb1 = *(const float4*)(Bg + (size_t)64 * K + k0);
        }

        const uint32_t baseA = sA + (uint32_t)buf * (BM * BKP * 4);
        const uint32_t baseB = sB + (uint32_t)buf * (BN * BKP * 4);
#pragma unroll
        for (int kh = 0; kh < 2; kh++) {
            uint32_t af[4][4];
            uint32_t bf[4][2];
#pragma unroll
            for (int mt = 0; mt < 4; mt++) {
                uint32_t addr = baseA + aRowOff + (uint32_t)mt * (16 * BKP * 4) + kh * 32;
                ldm_x4(af[mt][0], af[mt][1], af[mt][2], af[mt][3], addr);
            }
#pragma unroll
            for (int jp = 0; jp < 2; jp++) {
                uint32_t addr = baseB + bRowOff + (uint32_t)jp * (16 * BKP * 4) + kh * 32;
                uint32_t r0, r1, r2, r3;
                ldm_x4(r0, r1, r2, r3, addr);
                bf[2 * jp][0] = r0; bf[2 * jp][1] = r1;
                bf[2 * jp + 1][0] = r2; bf[2 * jp + 1][1] = r3;
            }
#pragma unroll
            for (int mt = 0; mt < 4; mt++)
#pragma unroll
                for (int nt = 0; nt < 4; nt++)
                    mma_tf32(c[mt][nt], af[mt], bf[nt]);
        }

        if (more) {
            const int nb = buf ^ 1;
            float* a0 = &As[nb][stRow];
            a0[0] = __uint_as_float(f2tf32(pa0.x)); a0[1] = __uint_as_float(f2tf32(pa0.y));
            a0[2] = __uint_as_float(f2tf32(pa0.z)); a0[3] = __uint_as_float(f2tf32(pa0.w));
            float* a1 = &As[nb][stRow + 64 * BKP];
            a1[0] = __uint_as_float(f2tf32(pa1.x)); a1[1] = __uint_as_float(f2tf32(pa1.y));
            a1[2] = __uint_as_float(f2tf32(pa1.z)); a1[3] = __uint_as_float(f2tf32(pa1.w));
            float* b0 = &Bs[nb][stRow];
            b0[0] = __uint_as_float(f2tf32(pb0.x)); b0[1] = __uint_as_float(f2tf32(pb0.y));
            b0[2] = __uint_as_float(f2tf32(pb0.z)); b0[3] = __uint_as_float(f2tf32(pb0.w));
            float* b1 = &Bs[nb][stRow + 64 * BKP];
            b1[0] = __uint_as_float(f2tf32(pb1.x)); b1[1] = __uint_as_float(f2tf32(pb1.y));
            b1[2] = __uint_as_float(f2tf32(pb1.z)); b1[3] = __uint_as_float(f2tf32(pb1.w));
            __syncthreads();
        }
    }

    // Epilogue
    const int er = lane >> 2;          // 0..7
    const int ec = (lane & 3) * 2;     // 0,2,4,6
#pragma unroll
    for (int mt = 0; mt < 4; mt++) {
        const int m = bm + wm + mt * 16 + er;
#pragma unroll
        for (int nt = 0; nt < 4; nt++) {
            const int n = bn + wn + nt * 8 + ec;
            float2 v0 = make_float2(c[mt][nt][0], c[mt][nt][1]);
            float2 v1 = make_float2(c[mt][nt][2], c[mt][nt][3]);
            if (EPI >= 1) {
                float bb0 = bias[n], bb1 = bias[n + 1];
                v0.x += bb0; v0.y += bb1;
                v1.x += bb0; v1.y += bb1;
            }
            if (EPI == 2) {
                v0.x = fmaxf(v0.x, 0.f); v0.y = fmaxf(v0.y, 0.f);
                v1.x = fmaxf(v1.x, 0.f); v1.y = fmaxf(v1.y, 0.f);
            }
            *(float2*)(C + (size_t)m * N + n)       = v0;
            *(float2*)(C + (size_t)(m + 8) * N + n) = v1;
        }
    }
}

// ============================ small kernels ================================
__global__ void k_transpose(const float* __restrict__ src, float* __restrict__ dst)
{
    __shared__ float t[32][33];
    int bx = blockIdx.x * 32, by = blockIdx.y * 32;
    int x = bx + threadIdx.x;
#pragma unroll
    for (int j = 0; j < 32; j += 8)
        t[threadIdx.y + j][threadIdx.x] = src[(size_t)(by + threadIdx.y + j) * D + x];
    __syncthreads();
    int ox = by + threadIdx.x;
#pragma unroll
    for (int j = 0; j < 32; j += 8)
        dst[(size_t)(bx + threadIdx.y + j) * D + ox] = t[threadIdx.x][threadIdx.y + j];
}

__global__ void k_gather(const float* __restrict__ a, const float* __restrict__ b,
                         const float* __restrict__ c)
{
    int o = blockIdx.x * 256 + threadIdx.x;
    int n = o / D;
    int d = o - n * D;
    int t = d % 3;
    const float* s = (t == 0) ? a : ((t == 1) ? b : c);
    g_feats[o] = s[n * (D / 3) + d / 3];
}

__global__ void k_norm()
{
    int i = blockIdx.x;
    float s = 0.f;
    for (int k = threadIdx.x; k < D; k += 256) {
        float v = g_feats[i * D + k];
        s = fmaf(v, v, s);
    }
    __shared__ float sh[256];
    sh[threadIdx.x] = s; __syncthreads();
    for (int t = 128; t > 0; t >>= 1) {
        if (threadIdx.x < t) sh[threadIdx.x] += sh[threadIdx.x + t];
        __syncthreads();
    }
    if (threadIdx.x == 0) g_nrm[i] = fmaxf(sqrtf(sh[0]), 1e-8f);
}

__global__ void k_sim()
{
    int i = blockIdx.x;
    __shared__ float fi[D];
    for (int k = threadIdx.x; k < D; k += 256) fi[k] = g_feats[i * D + k];
    __syncthreads();
    int warp = threadIdx.x >> 5, lane = threadIdx.x & 31;
    float ni = g_nrm[i];
    for (int jj = 0; jj < 16; jj++) {
        int j = warp * 16 + jj;
        float s = 0.f;
        for (int k = lane; k < D; k += 32) s = fmaf(fi[k], g_feats[j * D + k], s);
        for (int o = 16; o > 0; o >>= 1) s += __shfl_down_sync(0xffffffffu, s, o);
        if (lane == 0) g_sim[i * S + j] = s / (ni * g_nrm[j]);
    }
}

__global__ void k_simnorm()
{
    __shared__ float smn[256], smx[256];
    int tid = threadIdx.x;
    float mn = 1e30f, mx = -1e30f;
    for (int e = tid; e < S * S; e += 256) {
        float v = g_sim[e];
        mn = fminf(mn, v); mx = fmaxf(mx, v);
    }
    smn[tid] = mn; smx[tid] = mx;
    __syncthreads();
    for (int t = 128; t > 0; t >>= 1) {
        if (tid < t) {
            smn[tid] = fminf(smn[tid], smn[tid + t]);
            smx[tid] = fmaxf(smx[tid], smx[tid + t]);
        }
        __syncthreads();
    }
    float lo = smn[0];
    float inv = 1.f / (smx[0] - smn[0]);
    __syncthreads();
    for (int e = tid; e < S * S; e += 256) g_sim[e] = (g_sim[e] - lo) * inv;
    __syncthreads();
    if (tid < S) {
        float dg = 1.f;
        for (int i = 0; i < S; i++) dg += g_sim[i * S + tid];
        g_dinv[tid]   = rsqrtf(dg);
        g_deginv[tid] = 1.f / dg;
    }
}

__global__ void k_gcn_first(const float* __restrict__ gcn_b)
{
    int c = blockIdx.x;
    int d = blockIdx.y * 128 + threadIdx.x;
    __shared__ float col[S];
    col[threadIdx.x] = g_dinv[threadIdx.x] * g_sim[threadIdx.x * S + c];
    __syncthreads();
    float acc = 0.f;
#pragma unroll 8
    for (int i = 0; i < S; i++) acc = fmaf(col[i], g_xw[i * D + d], acc);
    float v = g_dinv[c] * acc + g_xw[c * D + d] * g_deginv[c] + gcn_b[d];
    g_x[c * D + d] = fmaxf(v, 0.f);
}

__global__ void k_gcn_rest(const float* __restrict__ gcn_b)
{
    int idx = blockIdx.x * 256 + threadIdx.x;
    int o = S * D + idx;
    int d = o % D;
    g_x[o] = fmaxf(g_xw[o] + gcn_b[d], 0.f);
}

__global__ void k_colsum()
{
    int d = blockIdx.x * 256 + threadIdx.x;
    float s = 0.f;
    for (int r = 0; r < S; r++) s += g_x[r * D + d];
    g_svec[d] = s;
}

__global__ void k_mvec(const float* __restrict__ W)
{
    int d = blockIdx.x * 256 + threadIdx.x;
    float acc = 0.f;
    for (int k = 0; k < D; k++) acc = fmaf(g_svec[k], W[k * D + d], acc);
    g_mvec[d] = acc;
}

__global__ void k_gi(const float* __restrict__ wih, const float* __restrict__ bih)
{
    int warp = threadIdx.x >> 5, lane = threadIdx.x & 31;
    int o = blockIdx.x * 8 + warp;
    float s = 0.f;
    for (int k = lane; k < D; k += 32) s = fmaf(g_mvec[k], wih[o * D + k], s);
    for (int off = 16; off > 0; off >>= 1) s += __shfl_down_sync(0xffffffffu, s, off);
    if (lane == 0) g_gi[o] = s + bih[o];
}

__global__ void k_gru(const float* __restrict__ bih)
{
    int o = blockIdx.x * 256 + threadIdx.x;
    int n = o / D;
    int d = o - n * D;
    float gir, giz, gin;
    if (n < S) { gir = g_gi[d];  giz = g_gi[D + d];  gin = g_gi[2 * D + d]; }
    else       { gir = bih[d];   giz = bih[D + d];   gin = bih[2 * D + d]; }
    size_t gb = (size_t)n * H3;
    float r  = 1.f / (1.f + expf(-(gir + g_gh[gb + d])));
    float z  = 1.f / (1.f + expf(-(giz + g_gh[gb + D + d])));
    float nn = tanhf(gin + r * g_gh[gb + 2 * D + d]);
    g_x[o] = (1.f - z) * nn + z * g_x[o];
}

__global__ void k_buildy(const float* __restrict__ hfeat)
{
    int o = blockIdx.x * 256 + threadIdx.x;
    g_feats[o] = hfeat[o % (BSN * D)] + fmaxf(g_x[o], 0.f);
}

__global__ void k_ln(const float* __restrict__ g1, const float* __restrict__ be1,
                     const float* __restrict__ g2, const float* __restrict__ be2,
                     const float* __restrict__ g3, const float* __restrict__ be3,
                     float* __restrict__ out)
{
    int r = blockIdx.x;
    int t = r / BSN;
    const float* gg = (t == 0) ? g1 : ((t == 1) ? g2 : g3);
    const float* bb = (t == 0) ? be1 : ((t == 1) ? be2 : be3);
    const float* z = g_gh + (size_t)r * D;
    int tid = threadIdx.x;
    float v0 = z[tid], v1 = z[tid + 256], v2 = z[tid + 512];
    __shared__ float sh[256];
    sh[tid] = v0 + v1 + v2; __syncthreads();
    for (int s = 128; s > 0; s >>= 1) {
        if (tid < s) sh[tid] += sh[tid + s];
        __syncthreads();
    }
    float mu = sh[0] * (1.f / 768.f);
    __syncthreads();
    float d0 = v0 - mu, d1 = v1 - mu, d2 = v2 - mu;
    sh[tid] = d0 * d0 + d1 * d1 + d2 * d2; __syncthreads();
    for (int s = 128; s > 0; s >>= 1) {
        if (tid < s) sh[tid] += sh[tid + s];
        __syncthreads();
    }
    float rstd = rsqrtf(sh[0] * (1.f / 768.f) + 1e-5f);
    float* o = out + (size_t)r * D;
    o[tid]       = d0 * rstd * gg[tid]       + bb[tid];
    o[tid + 256] = d1 * rstd * gg[tid + 256] + bb[tid + 256];
    o[tid + 512] = d2 * rstd * gg[tid + 512] + bb[tid + 512];
}

// ---------------------------------------------------------------------------
extern "C" void kernel_launch(void* const* d_in, const int* in_sizes, int n_in,
                              void* d_out, int out_size)
{
    const float* h_feature = (const float*)d_in[0];
    const float* h_con     = (const float*)d_in[1];
    const float* h_dep     = (const float*)d_in[2];
    const float* h_sem     = (const float*)d_in[3];
    const float* gcn_W     = (const float*)d_in[4];
    const float* gcn_b     = (const float*)d_in[5];
    const float* ggc_W     = (const float*)d_in[6];
    const float* gru_wih   = (const float*)d_in[7];
    const float* gru_whh   = (const float*)d_in[8];
    const float* gru_bih   = (const float*)d_in[9];
    const float* gru_bhh   = (const float*)d_in[10];
    const float* rW1[3]   = {(const float*)d_in[11], (const float*)d_in[17], (const float*)d_in[23]};
    const float* rb1[3]   = {(const float*)d_in[12], (const float*)d_in[18], (const float*)d_in[24]};
    const float* rW2[3]   = {(const float*)d_in[13], (const float*)d_in[19], (const float*)d_in[25]};
    const float* rb2[3]   = {(const float*)d_in[14], (const float*)d_in[20], (const float*)d_in[26]};
    const float* rg[3]    = {(const float*)d_in[15], (const float*)d_in[21], (const float*)d_in[27]};
    const float* rbeta[3] = {(const float*)d_in[16], (const float*)d_in[22], (const float*)d_in[28]};
    float* out = (float*)d_out;

    float *feats, *x, *xw, *gh, *wtg, *wt1, *wt2;
    cudaGetSymbolAddress((void**)&feats, g_feats);
    cudaGetSymbolAddress((void**)&x,     g_x);
    cudaGetSymbolAddress((void**)&xw,    g_xw);
    cudaGetSymbolAddress((void**)&gh,    g_gh);
    cudaGetSymbolAddress((void**)&wtg,   g_wtg);
    cudaGetSymbolAddress((void**)&wt1,   g_wt1);
    cudaGetSymbolAddress((void**)&wt2,   g_wt2);

    dim3 tb(32, 8);
    dim3 tg(D / 32, D / 32);

    // 1) feats gather + graph scalars + weight transposes
    k_gather<<<NN * D / 256, 256>>>(h_con, h_dep, h_sem);
    k_norm<<<S, 256>>>();
    k_sim<<<S, 256>>>();
    k_simnorm<<<1, 256>>>();
    k_transpose<<<tg, tb>>>(gcn_W, wtg);
    for (int t = 0; t < 3; t++) {
        k_transpose<<<tg, tb>>>(rW1[t], wt1 + (size_t)t * D * D);
        k_transpose<<<tg, tb>>>(rW2[t], wt2 + (size_t)t * D * D);
    }

    // 2) xw = feats @ gcn_W (B = gcn_W^T)
    tf32_gemm<0><<<dim3(D / BN, NN / BM), 256>>>(
        feats, wtg, wtg, wtg, nullptr, nullptr, nullptr, xw, NN, D, D, NN);

    // 3) GCN aggregation + relu -> g_x
    {
        dim3 g(S, D / 128);
        k_gcn_first<<<g, 128>>>(gcn_b);
    }
    k_gcn_rest<<<(NN - S) * D / 256, 256>>>(gcn_b);

    // 4) GatedGraphConv: 2 layers
    for (int l = 0; l < 2; l++) {
        k_colsum<<<3, 256>>>();
        k_mvec<<<3, 256>>>(ggc_W + (size_t)l * D * D);
        k_gi<<<H3 / 8, 256>>>(gru_wih, gru_bih);
        tf32_gemm<1><<<dim3(H3 / BN, NN / BM), 256>>>(
            x, gru_whh, gru_whh, gru_whh, gru_bhh, gru_bhh, gru_bhh,
            gh, NN, H3, D, NN);
        k_gru<<<NN * D / 256, 256>>>(gru_bih);
    }

    // 5) y = h_feature + relu(x)  (into g_feats)
    k_buildy<<<NN * D / 256, 256>>>(h_feature);

    // 6) three residual MLPs, batched over M=12288 with per-segment weights
    tf32_gemm<2><<<dim3(D / BN, NN / BM), 256>>>(
        feats, wt1, wt1 + (size_t)D * D, wt1 + 2 * (size_t)D * D,
        rb1[0], rb1[1], rb1[2], xw, NN, D, D, BSN);
    tf32_gemm<1><<<dim3(D / BN, NN / BM), 256>>>(
        xw, wt2, wt2 + (size_t)D * D, wt2 + 2 * (size_t)D * D,
        rb2[0], rb2[1], rb2[2], gh, NN, D, D, BSN);

    // 7) LayerNorm -> d_out
    k_ln<<<NN, 256>>>(rg[0], rbeta[0], rg[1], rbeta[1], rg[2], rbeta[2], out);
}

// round 4
// speedup vs baseline: 3.6097x; 1.2435x over previous
#include <cuda_runtime.h>
#include <cuda_fp16.h>
#include <math.h>
#include <stdint.h>

// Problem constants
constexpr int D   = 768;
constexpr int S   = 128;
constexpr int BSN = 4096;    // B*S
constexpr int NN  = 12288;   // 3*B*S
constexpr int H3  = 2304;    // 3*D

// Scratch (device globals — allocation-free rule)
__device__ float g_feats[NN * D];
__device__ float g_x[NN * D];
__device__ float g_xw[NN * D];
__device__ float g_gh[(size_t)NN * H3];
__device__ float g_sim[S * S];
__device__ float g_nrm[S];
__device__ float g_dinv[S];
__device__ float g_deginv[S];
__device__ float g_svec[D];
__device__ float g_mvec[D];
__device__ float g_gi[H3];
__device__ float g_wtg[D * D];        // gcn_W^T
__device__ float g_wt1[3 * D * D];    // rW1[t]^T
__device__ float g_wt2[3 * D * D];    // rW2[t]^T

// ============================ mma.sync helpers =============================
__device__ __forceinline__ uint32_t smem_u32(const void* p) {
    uint32_t a;
    asm("{ .reg .u64 t; cvta.to.shared.u64 t, %1; cvt.u32.u64 %0, t; }"
        : "=r"(a) : "l"(p));
    return a;
}
__device__ __forceinline__ void ldm_x4(uint32_t& r0, uint32_t& r1,
                                       uint32_t& r2, uint32_t& r3, uint32_t addr) {
    asm volatile("ldmatrix.sync.aligned.m8n8.x4.shared.b16 {%0,%1,%2,%3}, [%4];"
                 : "=r"(r0), "=r"(r1), "=r"(r2), "=r"(r3) : "r"(addr));
}
__device__ __forceinline__ void mma_f16(float* c, const uint32_t* a,
                                        const uint32_t* b) {
    asm volatile(
        "mma.sync.aligned.m16n8k16.row.col.f32.f16.f16.f32 "
        "{%0,%1,%2,%3}, {%4,%5,%6,%7}, {%8,%9}, {%0,%1,%2,%3};"
        : "+f"(c[0]), "+f"(c[1]), "+f"(c[2]), "+f"(c[3])
        : "r"(a[0]), "r"(a[1]), "r"(a[2]), "r"(a[3]), "r"(b[0]), "r"(b[1]));
}
__device__ __forceinline__ uint32_t pack_h2(float x, float y) {
    uint32_t r;
    __half2 h = __floats2half2_rn(x, y);
    r = *(uint32_t*)&h;
    return r;
}

// ===========================================================================
// fp16 mma.sync GEMM: C[m,n] = sum_k A[m,k]*B[n,k] (+bias, +relu)
// Block 128x128, BK=16 (one k16 step), 8 warps (2m x 4n), warp tile 64x32.
// Double-buffered fp16 SMEM (24-half padded rows), register prefetch,
// fp16 conversion at STS. B/bias per M-segment (rowSeg) batches 3 branches.
// ===========================================================================
constexpr int BM = 128, BN = 128, BK = 16, BKP = 24;   // BKP in halves
constexpr int ROWB = BKP * 2;                          // 48 bytes per row

template <int EPI>  // 0 none, 1 bias, 2 bias+relu
__global__ void __launch_bounds__(256, 2) f16_gemm(
    const float* __restrict__ A,
    const float* __restrict__ B0, const float* __restrict__ B1,
    const float* __restrict__ B2,
    const float* __restrict__ bias0, const float* __restrict__ bias1,
    const float* __restrict__ bias2,
    float* __restrict__ C, int M, int N, int K, int rowSeg)
{
    __shared__ __align__(16) __half As[2][BM * BKP];
    __shared__ __align__(16) __half Bs[2][BN * BKP];

    const int bm = blockIdx.y * BM;
    const int bn = blockIdx.x * BN;
    const int seg = bm / rowSeg;
    const float* Bp   = (seg == 0) ? B0 : ((seg == 1) ? B1 : B2);
    const float* bias = (seg == 0) ? bias0 : ((seg == 1) ? bias1 : bias2);

    const int tid  = threadIdx.x;
    const int lane = tid & 31;
    const int wid  = tid >> 5;
    const int wm   = (wid >> 2) * 64;   // warp m offset (0 / 64)
    const int wn   = (wid & 3) * 32;    // warp n offset (0/32/64/96)

    // GMEM load coords: thread loads 2 float4 from A and 2 from B per stage
    const int lr = tid >> 2;         // 0..63
    const int lc = (tid & 3) * 4;    // 0,4,8,12
    const float* Ag = A  + (size_t)(bm + lr) * K + lc;
    const float* Bg = Bp + (size_t)(bn + lr) * K + lc;

    const uint32_t sA = smem_u32(As);
    const uint32_t sB = smem_u32(Bs);
    // ldmatrix per-lane address components (bytes)
    const uint32_t aRowOff = (uint32_t)(wm + (lane & 15)) * ROWB + (lane >> 4) * 16;
    const uint32_t bRowOff = (uint32_t)(wn + (lane & 7) + ((lane >> 4) << 3)) * ROWB
                             + ((lane >> 3) & 1) * 16;
    // STS offsets (halves)
    const int stRow = lr * BKP + lc;

    float c[4][4][4];
#pragma unroll
    for (int i = 0; i < 4; i++)
#pragma unroll
        for (int j = 0; j < 4; j++)
#pragma unroll
            for (int q = 0; q < 4; q++) c[i][j][q] = 0.f;

    float4 pa0, pa1, pb0, pb1;
    // Prologue: load stage 0
    pa0 = *(const float4*)(Ag);
    pa1 = *(const float4*)(Ag + (size_t)64 * K);
    pb0 = *(const float4*)(Bg);
    pb1 = *(const float4*)(Bg + (size_t)64 * K);
    {
        uint2 v;
        v.x = pack_h2(pa0.x, pa0.y); v.y = pack_h2(pa0.z, pa0.w);
        *(uint2*)&As[0][stRow] = v;
        v.x = pack_h2(pa1.x, pa1.y); v.y = pack_h2(pa1.z, pa1.w);
        *(uint2*)&As[0][stRow + 64 * BKP] = v;
        v.x = pack_h2(pb0.x, pb0.y); v.y = pack_h2(pb0.z, pb0.w);
        *(uint2*)&Bs[0][stRow] = v;
        v.x = pack_h2(pb1.x, pb1.y); v.y = pack_h2(pb1.z, pb1.w);
        *(uint2*)&Bs[0][stRow + 64 * BKP] = v;
    }
    __syncthreads();

    const int NS = K / BK;
    for (int ks = 0; ks < NS; ks++) {
        const int buf = ks & 1;
        const bool more = (ks + 1) < NS;
        if (more) {
            const int k0 = (ks + 1) * BK;
            pa0 = *(const float4*)(Ag + k0);
            pa1 = *(const float4*)(Ag + (size_t)64 * K + k0);
            pb0 = *(const float4*)(Bg + k0);
            pb1 = *(const float4*)(Bg + (size_t)64 * K + k0);
        }

        const uint32_t baseA = sA + (uint32_t)buf * (BM * BKP * 2);
        const uint32_t baseB = sB + (uint32_t)buf * (BN * BKP * 2);
        {
            uint32_t af[4][4];
            uint32_t bf[4][2];
#pragma unroll
            for (int mt = 0; mt < 4; mt++) {
                uint32_t addr = baseA + aRowOff + (uint32_t)mt * (16 * ROWB);
                ldm_x4(af[mt][0], af[mt][1], af[mt][2], af[mt][3], addr);
            }
#pragma unroll
            for (int jp = 0; jp < 2; jp++) {
                uint32_t addr = baseB + bRowOff + (uint32_t)jp * (16 * ROWB);
                uint32_t r0, r1, r2, r3;
                ldm_x4(r0, r1, r2, r3, addr);
                bf[2 * jp][0] = r0;     bf[2 * jp][1] = r1;
                bf[2 * jp + 1][0] = r2; bf[2 * jp + 1][1] = r3;
            }
#pragma unroll
            for (int mt = 0; mt < 4; mt++)
#pragma unroll
                for (int nt = 0; nt < 4; nt++)
                    mma_f16(c[mt][nt], af[mt], bf[nt]);
        }

        if (more) {
            const int nb = buf ^ 1;
            uint2 v;
            v.x = pack_h2(pa0.x, pa0.y); v.y = pack_h2(pa0.z, pa0.w);
            *(uint2*)&As[nb][stRow] = v;
            v.x = pack_h2(pa1.x, pa1.y); v.y = pack_h2(pa1.z, pa1.w);
            *(uint2*)&As[nb][stRow + 64 * BKP] = v;
            v.x = pack_h2(pb0.x, pb0.y); v.y = pack_h2(pb0.z, pb0.w);
            *(uint2*)&Bs[nb][stRow] = v;
            v.x = pack_h2(pb1.x, pb1.y); v.y = pack_h2(pb1.z, pb1.w);
            *(uint2*)&Bs[nb][stRow + 64 * BKP] = v;
            __syncthreads();
        }
    }

    // Epilogue
    const int er = lane >> 2;          // 0..7
    const int ec = (lane & 3) * 2;     // 0,2,4,6
#pragma unroll
    for (int mt = 0; mt < 4; mt++) {
        const int m = bm + wm + mt * 16 + er;
#pragma unroll
        for (int nt = 0; nt < 4; nt++) {
            const int n = bn + wn + nt * 8 + ec;
            float2 v0 = make_float2(c[mt][nt][0], c[mt][nt][1]);
            float2 v1 = make_float2(c[mt][nt][2], c[mt][nt][3]);
            if (EPI >= 1) {
                float bb0 = bias[n], bb1 = bias[n + 1];
                v0.x += bb0; v0.y += bb1;
                v1.x += bb0; v1.y += bb1;
            }
            if (EPI == 2) {
                v0.x = fmaxf(v0.x, 0.f); v0.y = fmaxf(v0.y, 0.f);
                v1.x = fmaxf(v1.x, 0.f); v1.y = fmaxf(v1.y, 0.f);
            }
            *(float2*)(C + (size_t)m * N + n)       = v0;
            *(float2*)(C + (size_t)(m + 8) * N + n) = v1;
        }
    }
}

// ============================ small kernels ================================
__global__ void k_transpose(const float* __restrict__ src, float* __restrict__ dst)
{
    __shared__ float t[32][33];
    int bx = blockIdx.x * 32, by = blockIdx.y * 32;
    int x = bx + threadIdx.x;
#pragma unroll
    for (int j = 0; j < 32; j += 8)
        t[threadIdx.y + j][threadIdx.x] = src[(size_t)(by + threadIdx.y + j) * D + x];
    __syncthreads();
    int ox = by + threadIdx.x;
#pragma unroll
    for (int j = 0; j < 32; j += 8)
        dst[(size_t)(bx + threadIdx.y + j) * D + ox] = t[threadIdx.x][threadIdx.y + j];
}

__global__ void k_gather(const float* __restrict__ a, const float* __restrict__ b,
                         const float* __restrict__ c)
{
    int o = blockIdx.x * 256 + threadIdx.x;
    int n = o / D;
    int d = o - n * D;
    int t = d % 3;
    const float* s = (t == 0) ? a : ((t == 1) ? b : c);
    g_feats[o] = s[n * (D / 3) + d / 3];
}

__global__ void k_norm()
{
    int i = blockIdx.x;
    float s = 0.f;
    for (int k = threadIdx.x; k < D; k += 256) {
        float v = g_feats[i * D + k];
        s = fmaf(v, v, s);
    }
    __shared__ float sh[256];
    sh[threadIdx.x] = s; __syncthreads();
    for (int t = 128; t > 0; t >>= 1) {
        if (threadIdx.x < t) sh[threadIdx.x] += sh[threadIdx.x + t];
        __syncthreads();
    }
    if (threadIdx.x == 0) g_nrm[i] = fmaxf(sqrtf(sh[0]), 1e-8f);
}

__global__ void k_sim()
{
    int i = blockIdx.x;
    __shared__ float fi[D];
    for (int k = threadIdx.x; k < D; k += 256) fi[k] = g_feats[i * D + k];
    __syncthreads();
    int warp = threadIdx.x >> 5, lane = threadIdx.x & 31;
    float ni = g_nrm[i];
    for (int jj = 0; jj < 16; jj++) {
        int j = warp * 16 + jj;
        float s = 0.f;
        for (int k = lane; k < D; k += 32) s = fmaf(fi[k], g_feats[j * D + k], s);
        for (int o = 16; o > 0; o >>= 1) s += __shfl_down_sync(0xffffffffu, s, o);
        if (lane == 0) g_sim[i * S + j] = s / (ni * g_nrm[j]);
    }
}

__global__ void k_simnorm()
{
    __shared__ float smn[256], smx[256];
    int tid = threadIdx.x;
    float mn = 1e30f, mx = -1e30f;
    for (int e = tid; e < S * S; e += 256) {
        float v = g_sim[e];
        mn = fminf(mn, v); mx = fmaxf(mx, v);
    }
    smn[tid] = mn; smx[tid] = mx;
    __syncthreads();
    for (int t = 128; t > 0; t >>= 1) {
        if (tid < t) {
            smn[tid] = fminf(smn[tid], smn[tid + t]);
            smx[tid] = fmaxf(smx[tid], smx[tid + t]);
        }
        __syncthreads();
    }
    float lo = smn[0];
    float inv = 1.f / (smx[0] - smn[0]);
    __syncthreads();
    for (int e = tid; e < S * S; e += 256) g_sim[e] = (g_sim[e] - lo) * inv;
    __syncthreads();
    if (tid < S) {
        float dg = 1.f;
        for (int i = 0; i < S; i++) dg += g_sim[i * S + tid];
        g_dinv[tid]   = rsqrtf(dg);
        g_deginv[tid] = 1.f / dg;
    }
}

__global__ void k_gcn_first(const float* __restrict__ gcn_b)
{
    int c = blockIdx.x;
    int d = blockIdx.y * 128 + threadIdx.x;
    __shared__ float col[S];
    col[threadIdx.x] = g_dinv[threadIdx.x] * g_sim[threadIdx.x * S + c];
    __syncthreads();
    float acc = 0.f;
#pragma unroll 8
    for (int i = 0; i < S; i++) acc = fmaf(col[i], g_xw[i * D + d], acc);
    float v = g_dinv[c] * acc + g_xw[c * D + d] * g_deginv[c] + gcn_b[d];
    g_x[c * D + d] = fmaxf(v, 0.f);
}

__global__ void k_gcn_rest(const float* __restrict__ gcn_b)
{
    int idx = blockIdx.x * 256 + threadIdx.x;
    int o = S * D + idx;
    int d = o % D;
    g_x[o] = fmaxf(g_xw[o] + gcn_b[d], 0.f);
}

__global__ void k_colsum()
{
    int d = blockIdx.x * 256 + threadIdx.x;
    float s = 0.f;
    for (int r = 0; r < S; r++) s += g_x[r * D + d];
    g_svec[d] = s;
}

__global__ void k_mvec(const float* __restrict__ W)
{
    int d = blockIdx.x * 256 + threadIdx.x;
    float acc = 0.f;
    for (int k = 0; k < D; k++) acc = fmaf(g_svec[k], W[k * D + d], acc);
    g_mvec[d] = acc;
}

__global__ void k_gi(const float* __restrict__ wih, const float* __restrict__ bih)
{
    int warp = threadIdx.x >> 5, lane = threadIdx.x & 31;
    int o = blockIdx.x * 8 + warp;
    float s = 0.f;
    for (int k = lane; k < D; k += 32) s = fmaf(g_mvec[k], wih[o * D + k], s);
    for (int off = 16; off > 0; off >>= 1) s += __shfl_down_sync(0xffffffffu, s, off);
    if (lane == 0) g_gi[o] = s + bih[o];
}

__global__ void k_gru(const float* __restrict__ bih)
{
    int o = blockIdx.x * 256 + threadIdx.x;
    int n = o / D;
    int d = o - n * D;
    float gir, giz, gin;
    if (n < S) { gir = g_gi[d];  giz = g_gi[D + d];  gin = g_gi[2 * D + d]; }
    else       { gir = bih[d];   giz = bih[D + d];   gin = bih[2 * D + d]; }
    size_t gb = (size_t)n * H3;
    float r  = 1.f / (1.f + expf(-(gir + g_gh[gb + d])));
    float z  = 1.f / (1.f + expf(-(giz + g_gh[gb + D + d])));
    float nn = tanhf(gin + r * g_gh[gb + 2 * D + d]);
    g_x[o] = (1.f - z) * nn + z * g_x[o];
}

__global__ void k_buildy(const float* __restrict__ hfeat)
{
    int o = blockIdx.x * 256 + threadIdx.x;
    g_feats[o] = hfeat[o % (BSN * D)] + fmaxf(g_x[o], 0.f);
}

__global__ void k_ln(const float* __restrict__ g1, const float* __restrict__ be1,
                     const float* __restrict__ g2, const float* __restrict__ be2,
                     const float* __restrict__ g3, const float* __restrict__ be3,
                     float* __restrict__ out)
{
    int r = blockIdx.x;
    int t = r / BSN;
    const float* gg = (t == 0) ? g1 : ((t == 1) ? g2 : g3);
    const float* bb = (t == 0) ? be1 : ((t == 1) ? be2 : be3);
    const float* z = g_gh + (size_t)r * D;
    int tid = threadIdx.x;
    float v0 = z[tid], v1 = z[tid + 256], v2 = z[tid + 512];
    __shared__ float sh[256];
    sh[tid] = v0 + v1 + v2; __syncthreads();
    for (int s = 128; s > 0; s >>= 1) {
        if (tid < s) sh[tid] += sh[tid + s];
        __syncthreads();
    }
    float mu = sh[0] * (1.f / 768.f);
    __syncthreads();
    float d0 = v0 - mu, d1 = v1 - mu, d2 = v2 - mu;
    sh[tid] = d0 * d0 + d1 * d1 + d2 * d2; __syncthreads();
    for (int s = 128; s > 0; s >>= 1) {
        if (tid < s) sh[tid] += sh[tid + s];
        __syncthreads();
    }
    float rstd = rsqrtf(sh[0] * (1.f / 768.f) + 1e-5f);
    float* o = out + (size_t)r * D;
    o[tid]       = d0 * rstd * gg[tid]       + bb[tid];
    o[tid + 256] = d1 * rstd * gg[tid + 256] + bb[tid + 256];
    o[tid + 512] = d2 * rstd * gg[tid + 512] + bb[tid + 512];
}

// ---------------------------------------------------------------------------
extern "C" void kernel_launch(void* const* d_in, const int* in_sizes, int n_in,
                              void* d_out, int out_size)
{
    const float* h_feature = (const float*)d_in[0];
    const float* h_con     = (const float*)d_in[1];
    const float* h_dep     = (const float*)d_in[2];
    const float* h_sem     = (const float*)d_in[3];
    const float* gcn_W     = (const float*)d_in[4];
    const float* gcn_b     = (const float*)d_in[5];
    const float* ggc_W     = (const float*)d_in[6];
    const float* gru_wih   = (const float*)d_in[7];
    const float* gru_whh   = (const float*)d_in[8];
    const float* gru_bih   = (const float*)d_in[9];
    const float* gru_bhh   = (const float*)d_in[10];
    const float* rW1[3]   = {(const float*)d_in[11], (const float*)d_in[17], (const float*)d_in[23]};
    const float* rb1[3]   = {(const float*)d_in[12], (const float*)d_in[18], (const float*)d_in[24]};
    const float* rW2[3]   = {(const float*)d_in[13], (const float*)d_in[19], (const float*)d_in[25]};
    const float* rb2[3]   = {(const float*)d_in[14], (const float*)d_in[20], (const float*)d_in[26]};
    const float* rg[3]    = {(const float*)d_in[15], (const float*)d_in[21], (const float*)d_in[27]};
    const float* rbeta[3] = {(const float*)d_in[16], (const float*)d_in[22], (const float*)d_in[28]};
    float* out = (float*)d_out;

    float *feats, *x, *xw, *gh, *wtg, *wt1, *wt2;
    cudaGetSymbolAddress((void**)&feats, g_feats);
    cudaGetSymbolAddress((void**)&x,     g_x);
    cudaGetSymbolAddress((void**)&xw,    g_xw);
    cudaGetSymbolAddress((void**)&gh,    g_gh);
    cudaGetSymbolAddress((void**)&wtg,   g_wtg);
    cudaGetSymbolAddress((void**)&wt1,   g_wt1);
    cudaGetSymbolAddress((void**)&wt2,   g_wt2);

    dim3 tb(32, 8);
    dim3 tg(D / 32, D / 32);

    // 1) feats gather + graph scalars + weight transposes
    k_gather<<<NN * D / 256, 256>>>(h_con, h_dep, h_sem);
    k_norm<<<S, 256>>>();
    k_sim<<<S, 256>>>();
    k_simnorm<<<1, 256>>>();
    k_transpose<<<tg, tb>>>(gcn_W, wtg);
    for (int t = 0; t < 3; t++) {
        k_transpose<<<tg, tb>>>(rW1[t], wt1 + (size_t)t * D * D);
        k_transpose<<<tg, tb>>>(rW2[t], wt2 + (size_t)t * D * D);
    }

    // 2) xw = feats @ gcn_W (B = gcn_W^T)
    f16_gemm<0><<<dim3(D / BN, NN / BM), 256>>>(
        feats, wtg, wtg, wtg, nullptr, nullptr, nullptr, xw, NN, D, D, NN);

    // 3) GCN aggregation + relu -> g_x
    {
        dim3 g(S, D / 128);
        k_gcn_first<<<g, 128>>>(gcn_b);
    }
    k_gcn_rest<<<(NN - S) * D / 256, 256>>>(gcn_b);

    // 4) GatedGraphConv: 2 layers
    for (int l = 0; l < 2; l++) {
        k_colsum<<<3, 256>>>();
        k_mvec<<<3, 256>>>(ggc_W + (size_t)l * D * D);
        k_gi<<<H3 / 8, 256>>>(gru_wih, gru_bih);
        f16_gemm<1><<<dim3(H3 / BN, NN / BM), 256>>>(
            x, gru_whh, gru_whh, gru_whh, gru_bhh, gru_bhh, gru_bhh,
            gh, NN, H3, D, NN);
        k_gru<<<NN * D / 256, 256>>>(gru_bih);
    }

    // 5) y = h_feature + relu(x)  (into g_feats)
    k_buildy<<<NN * D / 256, 256>>>(h_feature);

    // 6) three residual MLPs, batched over M=12288 with per-segment weights
    f16_gemm<2><<<dim3(D / BN, NN / BM), 256>>>(
        feats, wt1, wt1 + (size_t)D * D, wt1 + 2 * (size_t)D * D,
        rb1[0], rb1[1], rb1[2], xw, NN, D, D, BSN);
    f16_gemm<1><<<dim3(D / BN, NN / BM), 256>>>(
        xw, wt2, wt2 + (size_t)D * D, wt2 + 2 * (size_t)D * D,
        rb2[0], rb2[1], rb2[2], gh, NN, D, D, BSN);

    // 7) LayerNorm -> d_out
    k_ln<<<NN, 256>>>(rg[0], rbeta[0], rg[1], rbeta[1], rg[2], rbeta[2], out);
}

// round 5
// speedup vs baseline: 3.9488x; 1.0939x over previous
#include <cuda_runtime.h>
#include <cuda_fp16.h>
#include <math.h>
#include <stdint.h>

// Problem constants
constexpr int D   = 768;
constexpr int S   = 128;
constexpr int BSN = 4096;    // B*S
constexpr int NN  = 12288;   // 3*B*S
constexpr int H3  = 2304;    // 3*D

// Scratch (device globals — allocation-free rule)
__device__ float  g_x[NN * D];
__device__ float  g_xw[NN * D];
__device__ float  g_gh[(size_t)NN * H3];
__device__ float  g_feats32[S * D];
__device__ __half g_featsh[NN * D];    // feats fp16; reused as y fp16
__device__ __half g_xh[NN * D];        // x fp16; reused as MLP hidden fp16
__device__ __half g_whh_h[H3 * D];
__device__ __half g_wtg_h[D * D];
__device__ __half g_wt1_h[3 * D * D];
__device__ __half g_wt2_h[3 * D * D];
__device__ float  g_sim[S * S];
__device__ float  g_nrm[S];
__device__ float  g_dinv[S];
__device__ float  g_deginv[S];
__device__ float  g_svec[D];
__device__ float  g_mvec[D];
__device__ float  g_gi[H3];

// ============================ mma.sync helpers =============================
__device__ __forceinline__ uint32_t smem_u32(const void* p) {
    uint32_t a;
    asm("{ .reg .u64 t; cvta.to.shared.u64 t, %1; cvt.u32.u64 %0, t; }"
        : "=r"(a) : "l"(p));
    return a;
}
__device__ __forceinline__ void ldm_x4(uint32_t& r0, uint32_t& r1,
                                       uint32_t& r2, uint32_t& r3, uint32_t addr) {
    asm volatile("ldmatrix.sync.aligned.m8n8.x4.shared.b16 {%0,%1,%2,%3}, [%4];"
                 : "=r"(r0), "=r"(r1), "=r"(r2), "=r"(r3) : "r"(addr));
}
__device__ __forceinline__ void mma_f16(float* c, const uint32_t* a,
                                        const uint32_t* b) {
    asm volatile(
        "mma.sync.aligned.m16n8k16.row.col.f32.f16.f16.f32 "
        "{%0,%1,%2,%3}, {%4,%5,%6,%7}, {%8,%9}, {%0,%1,%2,%3};"
        : "+f"(c[0]), "+f"(c[1]), "+f"(c[2]), "+f"(c[3])
        : "r"(a[0]), "r"(a[1]), "r"(a[2]), "r"(a[3]), "r"(b[0]), "r"(b[1]));
}
#define CP16(dst, src) \
    asm volatile("cp.async.cg.shared.global [%0], [%1], 16;" :: "r"(dst), "l"(src))
#define CP_COMMIT() asm volatile("cp.async.commit_group;" ::: "memory")
#define CP_WAIT1()  asm volatile("cp.async.wait_group 1;" ::: "memory")

// ===========================================================================
// fp16 mma.sync GEMM: C[m,n] = sum_k A[m,k]*B[n,k] (+bias, +relu)
// Block 128x256, BK=32, 8 warps (2m x 4n), warp tile 64x64.
// 3-stage cp.async pipeline, fp16 operands in GMEM, 80B-padded SMEM rows.
// B/bias per M-segment (rowSeg) batches the 3 MLP branches.
// ===========================================================================
constexpr int BM = 128, BN = 256, BK = 32;
constexpr int ROWB2 = 80;                       // bytes per SMEM row (32h + pad)
constexpr uint32_t A_BYTES = BM * ROWB2;        // 10240
constexpr uint32_t STAGE_BYTES = (BM + BN) * ROWB2;   // 30720
constexpr uint32_t SMEM_BYTES = 3 * STAGE_BYTES;      // 92160

template <int EPI, bool OUTH>  // EPI: 0 none, 1 bias, 2 bias+relu
__global__ void __launch_bounds__(256, 1) h_gemm(
    const __half* __restrict__ A,
    const __half* __restrict__ B0, const __half* __restrict__ B1,
    const __half* __restrict__ B2,
    const float* __restrict__ bias0, const float* __restrict__ bias1,
    const float* __restrict__ bias2,
    void* __restrict__ Cv, int M, int N, int K, int rowSeg)
{
    extern __shared__ char smem[];
    const int bn = blockIdx.x * BN;
    const int bm = blockIdx.y * BM;
    const int seg = bm / rowSeg;
    const __half* Bp  = (seg == 0) ? B0 : ((seg == 1) ? B1 : B2);
    const float* bias = (seg == 0) ? bias0 : ((seg == 1) ? bias1 : bias2);

    const int tid  = threadIdx.x;
    const int lane = tid & 31;
    const int wid  = tid >> 5;
    const int wm   = (wid >> 2) * 64;   // 0 / 64
    const int wn   = (wid & 3) * 64;    // 0/64/128/192

    const uint32_t sS = smem_u32(smem);

    // cp.async loader: A rows tid>>1 (128), B rows tid>>1 and +128 (256)
    const int lr = tid >> 1;
    const int ko = (tid & 1) * 16;      // halves (32B)
    const __half* Agl = A  + (size_t)(bm + lr) * K + ko;
    const __half* Bgl = Bp + (size_t)(bn + lr) * K + ko;
    const uint32_t aDst = (uint32_t)lr * ROWB2 + ko * 2;
    const uint32_t bDst = A_BYTES + (uint32_t)lr * ROWB2 + ko * 2;

#define LOAD_STAGE(s, kb) do { \
    const int _k0 = (kb) * BK; \
    const uint32_t _base = sS + (uint32_t)(s) * STAGE_BYTES; \
    const __half* _a = Agl + _k0; \
    CP16(_base + aDst, _a); CP16(_base + aDst + 16, _a + 8); \
    const __half* _b = Bgl + _k0; \
    CP16(_base + bDst, _b); CP16(_base + bDst + 16, _b + 8); \
    _b += (size_t)128 * K; \
    CP16(_base + bDst + 128 * ROWB2, _b); \
    CP16(_base + bDst + 128 * ROWB2 + 16, _b + 8); \
} while (0)

    float c[4][8][4];
#pragma unroll
    for (int i = 0; i < 4; i++)
#pragma unroll
        for (int j = 0; j < 8; j++)
#pragma unroll
            for (int q = 0; q < 4; q++) c[i][j][q] = 0.f;

    LOAD_STAGE(0, 0); CP_COMMIT();
    LOAD_STAGE(1, 1); CP_COMMIT();

    // per-lane ldmatrix offsets (bytes)
    const uint32_t aOff = (uint32_t)(wm + (lane & 15)) * ROWB2 + (lane >> 4) * 16;
    const uint32_t bOff = (uint32_t)(wn + (lane & 7) + ((lane >> 4) << 3)) * ROWB2
                          + ((lane >> 3) & 1) * 16;

    const int NS = K / BK;
    for (int ks = 0; ks < NS; ks++) {
        CP_WAIT1();
        __syncthreads();
        if (ks + 2 < NS) {
            const int s2 = (ks + 2) % 3;
            LOAD_STAGE(s2, ks + 2);
            CP_COMMIT();
        }
        const uint32_t aB = sS + (uint32_t)(ks % 3) * STAGE_BYTES;
        const uint32_t bB = aB + A_BYTES;
#pragma unroll
        for (int kh = 0; kh < 2; kh++) {
            uint32_t af[4][4], bf[8][2];
#pragma unroll
            for (int mt = 0; mt < 4; mt++)
                ldm_x4(af[mt][0], af[mt][1], af[mt][2], af[mt][3],
                       aB + aOff + kh * 32 + (uint32_t)mt * (16 * ROWB2));
#pragma unroll
            for (int jp = 0; jp < 4; jp++) {
                uint32_t r0, r1, r2, r3;
                ldm_x4(r0, r1, r2, r3,
                       bB + bOff + kh * 32 + (uint32_t)jp * (16 * ROWB2));
                bf[2 * jp][0] = r0;     bf[2 * jp][1] = r1;
                bf[2 * jp + 1][0] = r2; bf[2 * jp + 1][1] = r3;
            }
#pragma unroll
            for (int mt = 0; mt < 4; mt++)
#pragma unroll
                for (int nt = 0; nt < 8; nt++)
                    mma_f16(c[mt][nt], af[mt], bf[nt]);
        }
    }

    // Epilogue
    const int er = lane >> 2;
    const int ec = (lane & 3) * 2;
#pragma unroll
    for (int mt = 0; mt < 4; mt++) {
        const int m = bm + wm + mt * 16 + er;
#pragma unroll
        for (int nt = 0; nt < 8; nt++) {
            const int n = bn + wn + nt * 8 + ec;
            float2 v0 = make_float2(c[mt][nt][0], c[mt][nt][1]);
            float2 v1 = make_float2(c[mt][nt][2], c[mt][nt][3]);
            if (EPI >= 1) {
                float b0 = bias[n], b1 = bias[n + 1];
                v0.x += b0; v0.y += b1;
                v1.x += b0; v1.y += b1;
            }
            if (EPI == 2) {
                v0.x = fmaxf(v0.x, 0.f); v0.y = fmaxf(v0.y, 0.f);
                v1.x = fmaxf(v1.x, 0.f); v1.y = fmaxf(v1.y, 0.f);
            }
            if (OUTH) {
                __half* Ch = (__half*)Cv;
                *(__half2*)(Ch + (size_t)m * N + n)       = __floats2half2_rn(v0.x, v0.y);
                *(__half2*)(Ch + (size_t)(m + 8) * N + n) = __floats2half2_rn(v1.x, v1.y);
            } else {
                float* Cf = (float*)Cv;
                *(float2*)(Cf + (size_t)m * N + n)       = v0;
                *(float2*)(Cf + (size_t)(m + 8) * N + n) = v1;
            }
        }
    }
#undef LOAD_STAGE
}

// ============================ small kernels ================================
// fp32 [D,D] -> transposed fp16 dst[n*D+k] = src[k*D+n]
__global__ void k_transpose_h(const float* __restrict__ src, __half* __restrict__ dst)
{
    __shared__ float t[32][33];
    int bx = blockIdx.x * 32, by = blockIdx.y * 32;
    int x = bx + threadIdx.x;
#pragma unroll
    for (int j = 0; j < 32; j += 8)
        t[threadIdx.y + j][threadIdx.x] = src[(size_t)(by + threadIdx.y + j) * D + x];
    __syncthreads();
    int ox = by + threadIdx.x;
#pragma unroll
    for (int j = 0; j < 32; j += 8)
        dst[(size_t)(bx + threadIdx.y + j) * D + ox] = __float2half(t[threadIdx.x][threadIdx.y + j]);
}

__global__ void k_cvt_h(const float* __restrict__ src, __half* __restrict__ dst)
{
    int i = blockIdx.x * 256 + threadIdx.x;
    dst[i] = __float2half(src[i]);
}

__global__ void k_gather(const float* __restrict__ a, const float* __restrict__ b,
                         const float* __restrict__ c)
{
    int o = blockIdx.x * 256 + threadIdx.x;
    int n = o / D;
    int d = o - n * D;
    int t = d % 3;
    const float* s = (t == 0) ? a : ((t == 1) ? b : c);
    float v = s[n * (D / 3) + d / 3];
    g_featsh[o] = __float2half(v);
    if (o < S * D) g_feats32[o] = v;
}

__global__ void k_norm()
{
    int i = blockIdx.x;
    float s = 0.f;
    for (int k = threadIdx.x; k < D; k += 256) {
        float v = g_feats32[i * D + k];
        s = fmaf(v, v, s);
    }
    __shared__ float sh[256];
    sh[threadIdx.x] = s; __syncthreads();
    for (int t = 128; t > 0; t >>= 1) {
        if (threadIdx.x < t) sh[threadIdx.x] += sh[threadIdx.x + t];
        __syncthreads();
    }
    if (threadIdx.x == 0) g_nrm[i] = fmaxf(sqrtf(sh[0]), 1e-8f);
}

__global__ void k_sim()
{
    int i = blockIdx.x;
    __shared__ float fi[D];
    for (int k = threadIdx.x; k < D; k += 256) fi[k] = g_feats32[i * D + k];
    __syncthreads();
    int warp = threadIdx.x >> 5, lane = threadIdx.x & 31;
    float ni = g_nrm[i];
    for (int jj = 0; jj < 16; jj++) {
        int j = warp * 16 + jj;
        float s = 0.f;
        for (int k = lane; k < D; k += 32) s = fmaf(fi[k], g_feats32[j * D + k], s);
        for (int o = 16; o > 0; o >>= 1) s += __shfl_down_sync(0xffffffffu, s, o);
        if (lane == 0) g_sim[i * S + j] = s / (ni * g_nrm[j]);
    }
}

__global__ void k_simnorm()
{
    __shared__ float smn[256], smx[256];
    int tid = threadIdx.x;
    float mn = 1e30f, mx = -1e30f;
    for (int e = tid; e < S * S; e += 256) {
        float v = g_sim[e];
        mn = fminf(mn, v); mx = fmaxf(mx, v);
    }
    smn[tid] = mn; smx[tid] = mx;
    __syncthreads();
    for (int t = 128; t > 0; t >>= 1) {
        if (tid < t) {
            smn[tid] = fminf(smn[tid], smn[tid + t]);
            smx[tid] = fmaxf(smx[tid], smx[tid + t]);
        }
        __syncthreads();
    }
    float lo = smn[0];
    float inv = 1.f / (smx[0] - smn[0]);
    __syncthreads();
    for (int e = tid; e < S * S; e += 256) g_sim[e] = (g_sim[e] - lo) * inv;
    __syncthreads();
    if (tid < S) {
        float dg = 1.f;
        for (int i = 0; i < S; i++) dg += g_sim[i * S + tid];
        g_dinv[tid]   = rsqrtf(dg);
        g_deginv[tid] = 1.f / dg;
    }
}

__global__ void k_gcn_first(const float* __restrict__ gcn_b)
{
    int c = blockIdx.x;
    int d = blockIdx.y * 128 + threadIdx.x;
    __shared__ float col[S];
    col[threadIdx.x] = g_dinv[threadIdx.x] * g_sim[threadIdx.x * S + c];
    __syncthreads();
    float acc = 0.f;
#pragma unroll 8
    for (int i = 0; i < S; i++) acc = fmaf(col[i], g_xw[i * D + d], acc);
    float v = g_dinv[c] * acc + g_xw[c * D + d] * g_deginv[c] + gcn_b[d];
    v = fmaxf(v, 0.f);
    g_x[c * D + d] = v;
    g_xh[c * D + d] = __float2half(v);
}

__global__ void k_gcn_rest(const float* __restrict__ gcn_b)
{
    int idx = blockIdx.x * 256 + threadIdx.x;
    int o = S * D + idx;
    int d = o % D;
    float v = fmaxf(g_xw[o] + gcn_b[d], 0.f);
    g_x[o] = v;
    g_xh[o] = __float2half(v);
}

__global__ void k_colsum()
{
    int d = blockIdx.x * 256 + threadIdx.x;
    float s = 0.f;
    for (int r = 0; r < S; r++) s += g_x[r * D + d];
    g_svec[d] = s;
}

__global__ void k_mvec(const float* __restrict__ W)
{
    int d = blockIdx.x * 256 + threadIdx.x;
    float acc = 0.f;
    for (int k = 0; k < D; k++) acc = fmaf(g_svec[k], W[k * D + d], acc);
    g_mvec[d] = acc;
}

__global__ void k_gi(const float* __restrict__ wih, const float* __restrict__ bih)
{
    int warp = threadIdx.x >> 5, lane = threadIdx.x & 31;
    int o = blockIdx.x * 8 + warp;
    float s = 0.f;
    for (int k = lane; k < D; k += 32) s = fmaf(g_mvec[k], wih[o * D + k], s);
    for (int off = 16; off > 0; off >>= 1) s += __shfl_down_sync(0xffffffffu, s, off);
    if (lane == 0) g_gi[o] = s + bih[o];
}

__global__ void k_gru(const float* __restrict__ bih)
{
    int o = blockIdx.x * 256 + threadIdx.x;
    int n = o / D;
    int d = o - n * D;
    float gir, giz, gin;
    if (n < S) { gir = g_gi[d];  giz = g_gi[D + d];  gin = g_gi[2 * D + d]; }
    else       { gir = bih[d];   giz = bih[D + d];   gin = bih[2 * D + d]; }
    size_t gb = (size_t)n * H3;
    float r  = 1.f / (1.f + expf(-(gir + g_gh[gb + d])));
    float z  = 1.f / (1.f + expf(-(giz + g_gh[gb + D + d])));
    float nn = tanhf(gin + r * g_gh[gb + 2 * D + d]);
    float out = (1.f - z) * nn + z * g_x[o];
    g_x[o] = out;
    g_xh[o] = __float2half(out);
}

// y = h_feature + relu(x) -> fp16 into g_featsh (GEMM input only)
__global__ void k_buildy(const float* __restrict__ hfeat)
{
    int o = blockIdx.x * 256 + threadIdx.x;
    g_featsh[o] = __float2half(hfeat[o % (BSN * D)] + fmaxf(g_x[o], 0.f));
}

__global__ void k_ln(const float* __restrict__ g1, const float* __restrict__ be1,
                     const float* __restrict__ g2, const float* __restrict__ be2,
                     const float* __restrict__ g3, const float* __restrict__ be3,
                     float* __restrict__ out)
{
    int r = blockIdx.x;
    int t = r / BSN;
    const float* gg = (t == 0) ? g1 : ((t == 1) ? g2 : g3);
    const float* bb = (t == 0) ? be1 : ((t == 1) ? be2 : be3);
    const float* z = g_gh + (size_t)r * D;
    int tid = threadIdx.x;
    float v0 = z[tid], v1 = z[tid + 256], v2 = z[tid + 512];
    __shared__ float sh[256];
    sh[tid] = v0 + v1 + v2; __syncthreads();
    for (int s = 128; s > 0; s >>= 1) {
        if (tid < s) sh[tid] += sh[tid + s];
        __syncthreads();
    }
    float mu = sh[0] * (1.f / 768.f);
    __syncthreads();
    float d0 = v0 - mu, d1 = v1 - mu, d2 = v2 - mu;
    sh[tid] = d0 * d0 + d1 * d1 + d2 * d2; __syncthreads();
    for (int s = 128; s > 0; s >>= 1) {
        if (tid < s) sh[tid] += sh[tid + s];
        __syncthreads();
    }
    float rstd = rsqrtf(sh[0] * (1.f / 768.f) + 1e-5f);
    float* o = out + (size_t)r * D;
    o[tid]       = d0 * rstd * gg[tid]       + bb[tid];
    o[tid + 256] = d1 * rstd * gg[tid + 256] + bb[tid + 256];
    o[tid + 512] = d2 * rstd * gg[tid + 512] + bb[tid + 512];
}

// ---------------------------------------------------------------------------
extern "C" void kernel_launch(void* const* d_in, const int* in_sizes, int n_in,
                              void* d_out, int out_size)
{
    const float* h_feature = (const float*)d_in[0];
    const float* h_con     = (const float*)d_in[1];
    const float* h_dep     = (const float*)d_in[2];
    const float* h_sem     = (const float*)d_in[3];
    const float* gcn_W     = (const float*)d_in[4];
    const float* gcn_b     = (const float*)d_in[5];
    const float* ggc_W     = (const float*)d_in[6];
    const float* gru_wih   = (const float*)d_in[7];
    const float* gru_whh   = (const float*)d_in[8];
    const float* gru_bih   = (const float*)d_in[9];
    const float* gru_bhh   = (const float*)d_in[10];
    const float* rW1[3]   = {(const float*)d_in[11], (const float*)d_in[17], (const float*)d_in[23]};
    const float* rb1[3]   = {(const float*)d_in[12], (const float*)d_in[18], (const float*)d_in[24]};
    const float* rW2[3]   = {(const float*)d_in[13], (const float*)d_in[19], (const float*)d_in[25]};
    const float* rb2[3]   = {(const float*)d_in[14], (const float*)d_in[20], (const float*)d_in[26]};
    const float* rg[3]    = {(const float*)d_in[15], (const float*)d_in[21], (const float*)d_in[27]};
    const float* rbeta[3] = {(const float*)d_in[16], (const float*)d_in[22], (const float*)d_in[28]};
    float* out = (float*)d_out;

    float *x, *xw, *gh;
    __half *featsh, *xh, *whh_h, *wtg_h, *wt1_h, *wt2_h;
    cudaGetSymbolAddress((void**)&x,      g_x);
    cudaGetSymbolAddress((void**)&xw,     g_xw);
    cudaGetSymbolAddress((void**)&gh,     g_gh);
    cudaGetSymbolAddress((void**)&featsh, g_featsh);
    cudaGetSymbolAddress((void**)&xh,     g_xh);
    cudaGetSymbolAddress((void**)&whh_h,  g_whh_h);
    cudaGetSymbolAddress((void**)&wtg_h,  g_wtg_h);
    cudaGetSymbolAddress((void**)&wt1_h,  g_wt1_h);
    cudaGetSymbolAddress((void**)&wt2_h,  g_wt2_h);

    cudaFuncSetAttribute(h_gemm<0, false>, cudaFuncAttributeMaxDynamicSharedMemorySize, SMEM_BYTES);
    cudaFuncSetAttribute(h_gemm<1, false>, cudaFuncAttributeMaxDynamicSharedMemorySize, SMEM_BYTES);
    cudaFuncSetAttribute(h_gemm<2, true>,  cudaFuncAttributeMaxDynamicSharedMemorySize, SMEM_BYTES);

    dim3 tb(32, 8);
    dim3 tg(D / 32, D / 32);

    // 1) feats gather + graph scalars + fp16 weight prep
    k_gather<<<NN * D / 256, 256>>>(h_con, h_dep, h_sem);
    k_norm<<<S, 256>>>();
    k_sim<<<S, 256>>>();
    k_simnorm<<<1, 256>>>();
    k_transpose_h<<<tg, tb>>>(gcn_W, wtg_h);
    for (int t = 0; t < 3; t++) {
        k_transpose_h<<<tg, tb>>>(rW1[t], wt1_h + (size_t)t * D * D);
        k_transpose_h<<<tg, tb>>>(rW2[t], wt2_h + (size_t)t * D * D);
    }
    k_cvt_h<<<H3 * D / 256, 256>>>(gru_whh, whh_h);

    // 2) xw = feats @ gcn_W (B = gcn_W^T fp16)
    h_gemm<0, false><<<dim3(D / BN, NN / BM), 256, SMEM_BYTES>>>(
        featsh, wtg_h, wtg_h, wtg_h, nullptr, nullptr, nullptr,
        xw, NN, D, D, NN);

    // 3) GCN aggregation + relu -> g_x (+fp16 copy)
    {
        dim3 g(S, D / 128);
        k_gcn_first<<<g, 128>>>(gcn_b);
    }
    k_gcn_rest<<<(NN - S) * D / 256, 256>>>(gcn_b);

    // 4) GatedGraphConv: 2 layers
    for (int l = 0; l < 2; l++) {
        k_colsum<<<3, 256>>>();
        k_mvec<<<3, 256>>>(ggc_W + (size_t)l * D * D);
        k_gi<<<H3 / 8, 256>>>(gru_wih, gru_bih);
        h_gemm<1, false><<<dim3(H3 / BN, NN / BM), 256, SMEM_BYTES>>>(
            xh, whh_h, whh_h, whh_h, gru_bhh, gru_bhh, gru_bhh,
            gh, NN, H3, D, NN);
        k_gru<<<NN * D / 256, 256>>>(gru_bih);
    }

    // 5) y = h_feature + relu(x) -> fp16 (into g_featsh)
    k_buildy<<<NN * D / 256, 256>>>(h_feature);

    // 6) three residual MLPs, batched over M=12288 with per-segment weights
    h_gemm<2, true><<<dim3(D / BN, NN / BM), 256, SMEM_BYTES>>>(
        featsh, wt1_h, wt1_h + (size_t)D * D, wt1_h + 2 * (size_t)D * D,
        rb1[0], rb1[1], rb1[2], xh, NN, D, D, BSN);
    h_gemm<1, false><<<dim3(D / BN, NN / BM), 256, SMEM_BYTES>>>(
        xh, wt2_h, wt2_h + (size_t)D * D, wt2_h + 2 * (size_t)D * D,
        rb2[0], rb2[1], rb2[2], gh, NN, D, D, BSN);

    // 7) LayerNorm -> d_out
    k_ln<<<NN, 256>>>(rg[0], rbeta[0], rg[1], rbeta[1], rg[2], rbeta[2], out);
}